// round 4
// baseline (speedup 1.0000x reference)
#include <cuda_runtime.h>
#include <cuda_bf16.h>
#include <math.h>

// Inputs (metadata order):
//   0: density  float32 [M]
//   1: rgb      float32 [M,3]
//   2: bg       float32 [3]
//   3: shift    float32 [1]
//   4: interval float32 [1]
//   5: ray_id   int32   [M]   (sorted ascending)
//   6: n_rays   int32   [1]
// Output: rgb_marched float32 [N,3]

#define FULL_MASK 0xFFFFFFFFu

__global__ __launch_bounds__(256, 8)
void dvgo_render_kernel(const float* __restrict__ density,
                        const float* __restrict__ rgb,
                        const float* __restrict__ bg,
                        const float* __restrict__ shift_p,
                        const float* __restrict__ interval_p,
                        const int*   __restrict__ ray_id,
                        float* __restrict__ out,
                        int M, int n_rays)
{
    const int warp = (blockIdx.x * blockDim.x + threadIdx.x) >> 5;
    const int lane = threadIdx.x & 31;
    if (warp >= n_rays) return;

    const float shift    = __ldg(shift_p);
    const float interval = __ldg(interval_p);
    const int   r        = warp;

    // lower_bound(r): first index with ray_id[i] >= r
    // (uniform across the warp; all lanes hit the same address -> broadcast)
    int lo = 0, hi = M;
    while (lo < hi) {
        int mid = (lo + hi) >> 1;
        if (__ldg(ray_id + mid) < r) lo = mid + 1; else hi = mid;
    }
    const int start = lo;
    // lower_bound(r+1), starting from `start`
    hi = M;
    while (lo < hi) {
        int mid = (lo + hi) >> 1;
        if (__ldg(ray_id + mid) <= r) lo = mid + 1; else hi = mid;
    }
    const int end = lo;

    float carry = 0.0f;               // running sum of log(1-alpha) over the segment
    float acc_r = 0.0f, acc_g = 0.0f, acc_b = 0.0f;

    const int n = end - start;
    const int n_iter = (n + 31) >> 5; // uniform per warp

    for (int it = 0; it < n_iter; it++) {
        const int i = start + (it << 5) + lane;
        const bool valid = (i < end);

        // log(1-alpha) = -interval * softplus(density + shift)
        float lt = 0.0f;
        float cr = 0.0f, cg = 0.0f, cb = 0.0f;
        if (valid) {
            float x  = __ldg(density + i) + shift;
            float sp = fmaxf(x, 0.0f) + log1pf(__expf(-fabsf(x)));
            lt = -interval * sp;
            cr = __ldg(rgb + 3 * i + 0);
            cg = __ldg(rgb + 3 * i + 1);
            cb = __ldg(rgb + 3 * i + 2);
        }

        // warp inclusive scan of lt
        float scan = lt;
        #pragma unroll
        for (int off = 1; off < 32; off <<= 1) {
            float v = __shfl_up_sync(FULL_MASK, scan, off);
            if (lane >= off) scan += v;
        }
        const float excl = carry + (scan - lt);   // exclusive prefix (log T_i)

        // weight = alpha * T = (-expm1(lt)) * exp(logT)
        if (valid) {
            float w = -expm1f(lt) * __expf(excl);
            acc_r = fmaf(w, cr, acc_r);
            acc_g = fmaf(w, cg, acc_g);
            acc_b = fmaf(w, cb, acc_b);
        }

        // propagate chunk total
        carry += __shfl_sync(FULL_MASK, scan, 31);
    }

    // warp reduction of the rgb accumulators
    #pragma unroll
    for (int off = 16; off >= 1; off >>= 1) {
        acc_r += __shfl_xor_sync(FULL_MASK, acc_r, off);
        acc_g += __shfl_xor_sync(FULL_MASK, acc_g, off);
        acc_b += __shfl_xor_sync(FULL_MASK, acc_b, off);
    }

    if (lane == 0) {
        const float ainv = __expf(carry);         // final transmittance
        out[3 * r + 0] = acc_r + ainv * __ldg(bg + 0);
        out[3 * r + 1] = acc_g + ainv * __ldg(bg + 1);
        out[3 * r + 2] = acc_b + ainv * __ldg(bg + 2);
    }
}

extern "C" void kernel_launch(void* const* d_in, const int* in_sizes, int n_in,
                              void* d_out, int out_size)
{
    const float* density  = (const float*)d_in[0];
    const float* rgb      = (const float*)d_in[1];
    const float* bg       = (const float*)d_in[2];
    const float* shift_p  = (const float*)d_in[3];
    const float* interval = (const float*)d_in[4];
    const int*   ray_id   = (const int*)d_in[5];
    float*       out      = (float*)d_out;

    const int M      = in_sizes[0];
    const int n_rays = out_size / 3;

    const int threads = 256;                 // 8 warps per block
    const int warps_per_block = threads / 32;
    const int blocks = (n_rays + warps_per_block - 1) / warps_per_block;

    dvgo_render_kernel<<<blocks, threads>>>(density, rgb, bg, shift_p, interval,
                                            ray_id, out, M, n_rays);
}

// round 8
// speedup vs baseline: 1.8726x; 1.8726x over previous
#include <cuda_runtime.h>
#include <cuda_bf16.h>
#include <math.h>

// Inputs (metadata order):
//   0: density  float32 [M]
//   1: rgb      float32 [M,3]
//   2: bg       float32 [3]
//   3: shift    float32 [1]
//   4: interval float32 [1]
//   5: ray_id   int32   [M]   (sorted ascending)
//   6: n_rays   int32   [1]
// Output: rgb_marched float32 [N,3]

#define FULL_MASK 0xFFFFFFFFu
#define WARPS_PER_BLOCK 8

// Warp-cooperative 32-ary lower_bound: first index i in [0,M) with ray_id[i] >= r.
// All lanes participate; result is uniform across the warp.
__device__ __forceinline__ int warp_lower_bound(const int* __restrict__ ray_id,
                                                int M, int r, int lane)
{
    int lo = 0, hi = M;                 // invariant: answer in [lo, hi]
    while (hi - lo > 32) {
        const long long w = (long long)(hi - lo);
        const int pos = lo + (int)(w * (lane + 1) / 33);   // strictly inside (lo, hi)
        const int v = __ldg(ray_id + pos);
        const unsigned mask = __ballot_sync(FULL_MASK, v < r);
        if (mask == 0u) {
            hi = lo + (int)(w / 33);                        // answer <= pos of lane 0
        } else {
            const int h = 31 - __clz(mask);                 // highest lane with v < r
            const int nlo = lo + (int)(w * (h + 1) / 33) + 1;
            const int nhi = (h == 31) ? hi : (lo + (int)(w * (h + 2) / 33));
            lo = nlo; hi = nhi;
        }
    }
    // Final: probe lo..lo+31 directly.
    const int pos = lo + lane;
    const int v = (pos < hi) ? __ldg(ray_id + pos) : 0x7FFFFFFF;
    const unsigned mask = __ballot_sync(FULL_MASK, v >= r);
    return mask ? (lo + __ffs(mask) - 1) : hi;
}

__global__ __launch_bounds__(256, 8)
void dvgo_render_kernel(const float* __restrict__ density,
                        const float* __restrict__ rgb,
                        const float* __restrict__ bg,
                        const float* __restrict__ shift_p,
                        const float* __restrict__ interval_p,
                        const int*   __restrict__ ray_id,
                        float* __restrict__ out,
                        int M, int n_rays)
{
    __shared__ int s_start[WARPS_PER_BLOCK + 1];

    const int wid  = threadIdx.x >> 5;
    const int lane = threadIdx.x & 31;
    const int base = blockIdx.x * WARPS_PER_BLOCK;
    const int ray  = base + wid;

    // Each warp finds the start of its own ray; the last warp also finds the
    // start of the block's one-past-the-end ray. end(w) == start(w+1).
    if (ray <= n_rays) {
        const int s = warp_lower_bound(ray_id, M, ray, lane);
        if (lane == 0) s_start[wid] = s;
        if (wid == WARPS_PER_BLOCK - 1) {
            const int nxt = base + WARPS_PER_BLOCK;
            const int s2 = (nxt <= n_rays) ? warp_lower_bound(ray_id, M, nxt, lane) : M;
            if (lane == 0) s_start[WARPS_PER_BLOCK] = s2;
        }
    } else if (lane == 0) {
        s_start[wid] = M;
    }
    __syncthreads();
    if (ray >= n_rays) return;

    const int start = s_start[wid];
    const int end   = s_start[wid + 1];

    const float shift    = __ldg(shift_p);
    const float interval = __ldg(interval_p);

    float Tc = 1.0f;                      // transmittance entering current chunk
    float ar = 0.0f, ag = 0.0f, ab = 0.0f;

    const int n_iter = (end - start + 31) >> 5;

    for (int it = 0; it < n_iter; it++) {
        const int i  = start + (it << 5) + lane;
        const int ic = min(i, end - 1);   // clamped: safe load, w==0 for tail lanes

        // log(1-alpha) = -interval * softplus(density + shift)
        const float x  = __ldg(density + ic) + shift;
        const float cr = __ldg(rgb + 3 * ic + 0);
        const float cg = __ldg(rgb + 3 * ic + 1);
        const float cb = __ldg(rgb + 3 * ic + 2);

        const float e  = __expf(-fabsf(x));
        const float sp = fmaxf(x, 0.0f) + __logf(1.0f + e);
        const float lt = (i < end) ? (-interval * sp) : 0.0f;

        // warp inclusive scan of lt
        float scan = lt;
        #pragma unroll
        for (int off = 1; off < 32; off <<= 1) {
            const float v = __shfl_up_sync(FULL_MASK, scan, off);
            if (lane >= off) scan += v;
        }

        // T after sample i (inclusive); weight = T_before - T_after.
        // Tail lanes have lt=0 -> Ti == Te -> w == 0 exactly.
        const float Ti = Tc * __expf(scan);
        float Te = __shfl_up_sync(FULL_MASK, Ti, 1);
        if (lane == 0) Te = Tc;
        const float w = Te - Ti;

        ar = fmaf(w, cr, ar);
        ag = fmaf(w, cg, ag);
        ab = fmaf(w, cb, ab);

        Tc = __shfl_sync(FULL_MASK, Ti, 31);   // carry transmittance to next chunk
    }

    // warp reduction of rgb accumulators
    #pragma unroll
    for (int off = 16; off >= 1; off >>= 1) {
        ar += __shfl_xor_sync(FULL_MASK, ar, off);
        ag += __shfl_xor_sync(FULL_MASK, ag, off);
        ab += __shfl_xor_sync(FULL_MASK, ab, off);
    }

    if (lane == 0) {
        out[3 * ray + 0] = ar + Tc * __ldg(bg + 0);
        out[3 * ray + 1] = ag + Tc * __ldg(bg + 1);
        out[3 * ray + 2] = ab + Tc * __ldg(bg + 2);
    }
}

extern "C" void kernel_launch(void* const* d_in, const int* in_sizes, int n_in,
                              void* d_out, int out_size)
{
    const float* density  = (const float*)d_in[0];
    const float* rgb      = (const float*)d_in[1];
    const float* bg       = (const float*)d_in[2];
    const float* shift_p  = (const float*)d_in[3];
    const float* interval = (const float*)d_in[4];
    const int*   ray_id   = (const int*)d_in[5];
    float*       out      = (float*)d_out;

    const int M      = in_sizes[0];
    const int n_rays = out_size / 3;

    const int threads = 32 * WARPS_PER_BLOCK;
    const int blocks  = (n_rays + WARPS_PER_BLOCK - 1) / WARPS_PER_BLOCK;

    dvgo_render_kernel<<<blocks, threads>>>(density, rgb, bg, shift_p, interval,
                                            ray_id, out, M, n_rays);
}